// round 2
// baseline (speedup 1.0000x reference)
#include <cuda_runtime.h>
#include <cstdint>

#define N_NODES 100000
#define N_EDGES 1600000
#define CH 64
#define EDIM 16
#define HID 32

// Scratch (static device globals — allocation-free)
__device__ float g_xw[N_NODES * CH];     // x @ W
__device__ float g_alpha[N_EDGES];       // edge gate
__device__ float g_deg[N_NODES];         // degree -> then dis = rsqrt(deg)
__device__ int   g_is64;                 // 1 if edge_index is int64, 0 if int32

// ---------------------------------------------------------------------------
// dtype detection: sample 64 entries as int64; valid range => int64 layout
// ---------------------------------------------------------------------------
__global__ void k_detect(const long long* __restrict__ ei64) {
    if (blockIdx.x == 0 && threadIdx.x == 0) {
        int ok = 1;
        #pragma unroll 1
        for (int i = 0; i < 64; ++i) {
            long long v = ei64[i];
            if (v < 0 || v >= N_NODES) { ok = 0; break; }
        }
        g_is64 = ok;
    }
}

__device__ __forceinline__ int edge_row(const void* ei, int e) {
    if (g_is64) return (int)((const long long*)ei)[e];
    return ((const int*)ei)[e];
}
__device__ __forceinline__ int edge_col(const void* ei, int e) {
    if (g_is64) return (int)((const long long*)ei)[(size_t)N_EDGES + e];
    return ((const int*)ei)[(size_t)N_EDGES + e];
}

// ---------------------------------------------------------------------------
// 0) zero the output accumulator (d_out is poisoned) and deg
// ---------------------------------------------------------------------------
__global__ void k_init(float* __restrict__ out) {
    int i = blockIdx.x * blockDim.x + threadIdx.x;
    if (i < N_NODES * CH) out[i] = 0.0f;
    if (i < N_NODES) g_deg[i] = 0.0f;
}

// ---------------------------------------------------------------------------
// 1) xw = x @ W   (W is [64,64] row-major, staged in smem)
// ---------------------------------------------------------------------------
__global__ void k_xw(const float* __restrict__ x, const float* __restrict__ W) {
    __shared__ float Ws[CH * CH];
    for (int i = threadIdx.x; i < CH * CH; i += blockDim.x) Ws[i] = W[i];
    __syncthreads();
    const int c  = threadIdx.x & 63;    // output channel
    const int ln = threadIdx.x >> 6;    // 0..3 node slot
    const int base = blockIdx.x * 64;
    for (int it = 0; it < 16; ++it) {
        int n = base + it * 4 + ln;
        if (n < N_NODES) {
            const float* xr = x + (size_t)n * CH;
            float acc = 0.0f;
            #pragma unroll
            for (int k = 0; k < CH; ++k) acc = fmaf(xr[k], Ws[k * CH + c], acc);
            g_xw[(size_t)n * CH + c] = acc;
        }
    }
}

// ---------------------------------------------------------------------------
// 2) edge MLP gate: alpha = sigmoid(silu(ea@W1+b1)@W2+b2); deg[col] += alpha
// ---------------------------------------------------------------------------
__global__ void k_edge(const float* __restrict__ ea,
                       const void* __restrict__ ei,
                       const float* __restrict__ W1, const float* __restrict__ b1,
                       const float* __restrict__ W2, const float* __restrict__ b2) {
    __shared__ float sW1[EDIM * HID];
    __shared__ float sb1[HID];
    __shared__ float sW2[HID];
    __shared__ float sb2;
    for (int i = threadIdx.x; i < EDIM * HID; i += blockDim.x) sW1[i] = W1[i];
    if (threadIdx.x < HID) { sb1[threadIdx.x] = b1[threadIdx.x]; sW2[threadIdx.x] = W2[threadIdx.x]; }
    if (threadIdx.x == 0) sb2 = b2[0];
    __syncthreads();

    int e = blockIdx.x * blockDim.x + threadIdx.x;
    if (e >= N_EDGES) return;

    float a[EDIM];
    const float4* p = (const float4*)(ea + (size_t)e * EDIM);
    #pragma unroll
    for (int i = 0; i < 4; ++i) {
        float4 v = p[i];
        a[4*i+0] = v.x; a[4*i+1] = v.y; a[4*i+2] = v.z; a[4*i+3] = v.w;
    }

    float acc = sb2;
    #pragma unroll
    for (int j = 0; j < HID; ++j) {
        float h = sb1[j];
        #pragma unroll
        for (int k = 0; k < EDIM; ++k) h = fmaf(a[k], sW1[k * HID + j], h);
        float s = h / (1.0f + __expf(-h));     // silu
        acc = fmaf(s, sW2[j], acc);
    }
    float alpha = 1.0f / (1.0f + __expf(-acc)); // sigmoid
    g_alpha[e] = alpha;

    atomicAdd(&g_deg[edge_col(ei, e)], alpha);
}

// ---------------------------------------------------------------------------
// 3) dis = deg > 0 ? rsqrt(deg) : 0   (in place)
// ---------------------------------------------------------------------------
__global__ void k_dis() {
    int n = blockIdx.x * blockDim.x + threadIdx.x;
    if (n < N_NODES) {
        float d = g_deg[n];
        g_deg[n] = (d > 0.0f) ? rsqrtf(d) : 0.0f;
    }
}

// ---------------------------------------------------------------------------
// 4) scatter: out[col] += xw[row] * (dis[row]*alpha*dis[col])
//    one warp per edge, 2 channels per lane (float2 gather + 2 REDs)
// ---------------------------------------------------------------------------
__global__ void k_scatter(const void* __restrict__ ei,
                          float* __restrict__ out) {
    int gwid = (blockIdx.x * blockDim.x + threadIdx.x) >> 5;
    int lane = threadIdx.x & 31;
    if (gwid >= N_EDGES) return;

    int row, col;
    float norm = 0.0f;
    if (lane == 0) {
        row = edge_row(ei, gwid);
        col = edge_col(ei, gwid);
        norm = g_deg[row] * g_alpha[gwid] * g_deg[col];
    }
    norm = __shfl_sync(0xffffffffu, norm, 0);
    row  = __shfl_sync(0xffffffffu, row, 0);
    col  = __shfl_sync(0xffffffffu, col, 0);

    const float2* src = (const float2*)(g_xw + (size_t)row * CH);
    float2 v = src[lane];
    float* dst = out + (size_t)col * CH + lane * 2;
    atomicAdd(dst + 0, v.x * norm);
    atomicAdd(dst + 1, v.y * norm);
}

// ---------------------------------------------------------------------------
// 5) h += b ; LayerNorm ; *gamma + beta ; silu ; + x   (one warp per node)
// ---------------------------------------------------------------------------
__global__ void k_ln(const float* __restrict__ x, const float* __restrict__ b,
                     const float* __restrict__ gamma, const float* __restrict__ beta,
                     float* __restrict__ out) {
    int node = (blockIdx.x * blockDim.x + threadIdx.x) >> 5;
    int lane = threadIdx.x & 31;
    if (node >= N_NODES) return;

    size_t base = (size_t)node * CH;
    float h0 = out[base + lane]      + b[lane];
    float h1 = out[base + lane + 32] + b[lane + 32];

    float s = h0 + h1;
    #pragma unroll
    for (int o = 16; o > 0; o >>= 1) s += __shfl_xor_sync(0xffffffffu, s, o);
    float mu = s * (1.0f / 64.0f);

    float d0 = h0 - mu, d1 = h1 - mu;
    float vs = d0 * d0 + d1 * d1;
    #pragma unroll
    for (int o = 16; o > 0; o >>= 1) vs += __shfl_xor_sync(0xffffffffu, vs, o);
    float inv = rsqrtf(vs * (1.0f / 64.0f) + 1e-5f);

    float y0 = fmaf(d0 * inv, gamma[lane],      beta[lane]);
    float y1 = fmaf(d1 * inv, gamma[lane + 32], beta[lane + 32]);
    y0 = y0 / (1.0f + __expf(-y0));   // silu
    y1 = y1 / (1.0f + __expf(-y1));

    out[base + lane]      = y0 + x[base + lane];
    out[base + lane + 32] = y1 + x[base + lane + 32];
}

// ---------------------------------------------------------------------------
extern "C" void kernel_launch(void* const* d_in, const int* in_sizes, int n_in,
                              void* d_out, int out_size) {
    const float* x     = (const float*)d_in[0];
    const void*  ei    = d_in[1];                 // int32 or int64 [2, E]
    const float* ea    = (const float*)d_in[2];
    const float* W     = (const float*)d_in[3];
    const float* b     = (const float*)d_in[4];
    const float* W1    = (const float*)d_in[5];
    const float* b1    = (const float*)d_in[6];
    const float* W2    = (const float*)d_in[7];
    const float* b2    = (const float*)d_in[8];
    const float* gamma = (const float*)d_in[9];
    const float* beta  = (const float*)d_in[10];
    float* out = (float*)d_out;

    // dtype detection for edge_index
    k_detect<<<1, 32>>>((const long long*)ei);

    // 0) zero accumulators
    k_init<<<(N_NODES * CH + 255) / 256, 256>>>(out);

    // 1) xw = x @ W
    k_xw<<<(N_NODES + 63) / 64, 256>>>(x, W);

    // 2) edge gate + degree
    k_edge<<<(N_EDGES + 255) / 256, 256>>>(ea, ei, W1, b1, W2, b2);

    // 3) dis
    k_dis<<<(N_NODES + 255) / 256, 256>>>();

    // 4) scatter-sum (one warp per edge, 8 warps per block)
    k_scatter<<<(N_EDGES + 7) / 8, 256>>>(ei, out);

    // 5) LayerNorm + silu + residual (one warp per node)
    k_ln<<<(N_NODES + 7) / 8, 256>>>(x, b, gamma, beta, out);
}

// round 3
// speedup vs baseline: 1.6486x; 1.6486x over previous
#include <cuda_runtime.h>
#include <cstdint>

#define N_NODES 100000
#define N_EDGES 1600000
#define CH 64
#define EDIM 16
#define HID 32
#define NB_SCAN ((N_NODES + 1023) / 1024)   // 98

// Scratch (static device globals — allocation-free)
__device__ float g_xw[N_NODES * CH];       // x @ W
__device__ float g_alpha[N_EDGES];         // edge gate
__device__ float g_deg[N_NODES];           // degree -> then dis = rsqrt(deg)
__device__ int   g_cnt[N_NODES];           // in-degree (edge count per col)
__device__ int   g_incl[N_NODES];          // inclusive scan within block
__device__ int   g_bsum[NB_SCAN];          // per-block totals
__device__ int   g_boff[NB_SCAN];          // exclusive block offsets
__device__ int   g_rowptr[N_NODES];        // CSR start per node
__device__ int   g_wptr[N_NODES];          // write cursor for placement
__device__ int   g_erow[N_EDGES];          // source node per CSR slot
__device__ float g_enorm[N_EDGES];         // norm per CSR slot
__device__ int   g_is64;                   // 1 if edge_index is int64

// ---------------------------------------------------------------------------
// dtype detection: sample 64 entries as int64; valid range => int64 layout
// ---------------------------------------------------------------------------
__global__ void k_detect(const long long* __restrict__ ei64) {
    if (threadIdx.x == 0) {
        int ok = 1;
        #pragma unroll 1
        for (int i = 0; i < 64; ++i) {
            long long v = ei64[i];
            if (v < 0 || v >= N_NODES) { ok = 0; break; }
        }
        g_is64 = ok;
    }
}

__device__ __forceinline__ int edge_row(const void* ei, int e) {
    if (g_is64) return (int)((const long long*)ei)[e];
    return ((const int*)ei)[e];
}
__device__ __forceinline__ int edge_col(const void* ei, int e) {
    if (g_is64) return (int)((const long long*)ei)[(size_t)N_EDGES + e];
    return ((const int*)ei)[(size_t)N_EDGES + e];
}

// ---------------------------------------------------------------------------
// 0) zero deg + cnt
// ---------------------------------------------------------------------------
__global__ void k_init() {
    int i = blockIdx.x * blockDim.x + threadIdx.x;
    if (i < N_NODES) { g_deg[i] = 0.0f; g_cnt[i] = 0; }
}

// ---------------------------------------------------------------------------
// 1) xw = x @ W   (W is [64,64] row-major, staged in smem)
// ---------------------------------------------------------------------------
__global__ void k_xw(const float* __restrict__ x, const float* __restrict__ W) {
    __shared__ float Ws[CH * CH];
    for (int i = threadIdx.x; i < CH * CH; i += blockDim.x) Ws[i] = W[i];
    __syncthreads();
    const int c  = threadIdx.x & 63;
    const int ln = threadIdx.x >> 6;
    const int base = blockIdx.x * 64;
    for (int it = 0; it < 16; ++it) {
        int n = base + it * 4 + ln;
        if (n < N_NODES) {
            const float* xr = x + (size_t)n * CH;
            float acc = 0.0f;
            #pragma unroll
            for (int k = 0; k < CH; ++k) acc = fmaf(xr[k], Ws[k * CH + c], acc);
            g_xw[(size_t)n * CH + c] = acc;
        }
    }
}

// ---------------------------------------------------------------------------
// 2) edge MLP gate + degree + count.  W1 transposed in smem -> LDS.128.
// ---------------------------------------------------------------------------
__global__ void k_edge(const float* __restrict__ ea,
                       const void* __restrict__ ei,
                       const float* __restrict__ W1, const float* __restrict__ b1,
                       const float* __restrict__ W2, const float* __restrict__ b2) {
    __shared__ __align__(16) float sW1t[HID * EDIM];   // [j][k] transposed
    __shared__ float sb1[HID];
    __shared__ float sW2[HID];
    __shared__ float sb2;
    for (int i = threadIdx.x; i < HID * EDIM; i += blockDim.x) {
        int j = i >> 4, k = i & 15;
        sW1t[i] = W1[k * HID + j];
    }
    if (threadIdx.x < HID) { sb1[threadIdx.x] = b1[threadIdx.x]; sW2[threadIdx.x] = W2[threadIdx.x]; }
    if (threadIdx.x == 0) sb2 = b2[0];
    __syncthreads();

    int e = blockIdx.x * blockDim.x + threadIdx.x;
    if (e >= N_EDGES) return;

    float4 a0, a1, a2, a3;
    {
        const float4* p = (const float4*)(ea + (size_t)e * EDIM);
        a0 = p[0]; a1 = p[1]; a2 = p[2]; a3 = p[3];
    }

    const float4* Wt = (const float4*)sW1t;
    float acc = sb2;
    #pragma unroll
    for (int j = 0; j < HID; ++j) {
        float4 w0 = Wt[j * 4 + 0], w1 = Wt[j * 4 + 1], w2 = Wt[j * 4 + 2], w3 = Wt[j * 4 + 3];
        float h = sb1[j];
        h = fmaf(a0.x, w0.x, h); h = fmaf(a0.y, w0.y, h); h = fmaf(a0.z, w0.z, h); h = fmaf(a0.w, w0.w, h);
        h = fmaf(a1.x, w1.x, h); h = fmaf(a1.y, w1.y, h); h = fmaf(a1.z, w1.z, h); h = fmaf(a1.w, w1.w, h);
        h = fmaf(a2.x, w2.x, h); h = fmaf(a2.y, w2.y, h); h = fmaf(a2.z, w2.z, h); h = fmaf(a2.w, w2.w, h);
        h = fmaf(a3.x, w3.x, h); h = fmaf(a3.y, w3.y, h); h = fmaf(a3.z, w3.z, h); h = fmaf(a3.w, w3.w, h);
        float s = __fdividef(h, 1.0f + __expf(-h));    // silu
        acc = fmaf(s, sW2[j], acc);
    }
    float alpha = __fdividef(1.0f, 1.0f + __expf(-acc)); // sigmoid
    g_alpha[e] = alpha;

    int col = edge_col(ei, e);
    atomicAdd(&g_deg[col], alpha);
    atomicAdd(&g_cnt[col], 1);
}

// ---------------------------------------------------------------------------
// 3a) per-block inclusive scan of cnt (1024/block)
// ---------------------------------------------------------------------------
__global__ void k_scan1() {
    int i = blockIdx.x * 1024 + threadIdx.x;
    int v = (i < N_NODES) ? g_cnt[i] : 0;
    int lane = threadIdx.x & 31, wid = threadIdx.x >> 5;
    int s = v;
    #pragma unroll
    for (int o = 1; o < 32; o <<= 1) {
        int t = __shfl_up_sync(0xffffffffu, s, o);
        if (lane >= o) s += t;
    }
    __shared__ int wsum[32];
    if (lane == 31) wsum[wid] = s;
    __syncthreads();
    if (wid == 0) {
        int t = wsum[lane];
        #pragma unroll
        for (int o = 1; o < 32; o <<= 1) {
            int u = __shfl_up_sync(0xffffffffu, t, o);
            if (lane >= o) t += u;
        }
        wsum[lane] = t;
    }
    __syncthreads();
    int incl = s + (wid > 0 ? wsum[wid - 1] : 0);
    if (i < N_NODES) g_incl[i] = incl;
    if (threadIdx.x == 1023) g_bsum[blockIdx.x] = incl;
}

// ---------------------------------------------------------------------------
// 3b) scan block sums (serial, tiny)
// ---------------------------------------------------------------------------
__global__ void k_scan2() {
    if (threadIdx.x == 0) {
        int run = 0;
        #pragma unroll 1
        for (int b = 0; b < NB_SCAN; ++b) { g_boff[b] = run; run += g_bsum[b]; }
    }
}

// ---------------------------------------------------------------------------
// 3c) finalize rowptr/wptr + dis = rsqrt(deg)
// ---------------------------------------------------------------------------
__global__ void k_final() {
    int i = blockIdx.x * blockDim.x + threadIdx.x;
    if (i < N_NODES) {
        int excl = g_incl[i] - g_cnt[i] + g_boff[i >> 10];
        g_rowptr[i] = excl;
        g_wptr[i] = excl;
        float d = g_deg[i];
        g_deg[i] = (d > 0.0f) ? rsqrtf(d) : 0.0f;
    }
}

// ---------------------------------------------------------------------------
// 4) placement: per edge, compute norm, drop (row, norm) into col's CSR slot
// ---------------------------------------------------------------------------
__global__ void k_place(const void* __restrict__ ei) {
    int e = blockIdx.x * blockDim.x + threadIdx.x;
    if (e >= N_EDGES) return;
    int row = edge_row(ei, e);
    int col = edge_col(ei, e);
    float norm = g_deg[row] * g_alpha[e] * g_deg[col];
    int pos = atomicAdd(&g_wptr[col], 1);
    g_erow[pos] = row;
    g_enorm[pos] = norm;
}

// ---------------------------------------------------------------------------
// 5) gather + bias + LayerNorm + SiLU + residual.  One warp per node,
//    each lane owns channels (2l, 2l+1).
// ---------------------------------------------------------------------------
__global__ void k_gather_ln(const float* __restrict__ x, const float* __restrict__ b,
                            const float* __restrict__ gamma, const float* __restrict__ beta,
                            float* __restrict__ out) {
    int node = (blockIdx.x * blockDim.x + threadIdx.x) >> 5;
    int lane = threadIdx.x & 31;
    if (node >= N_NODES) return;

    int start = g_rowptr[node];
    int cnt   = g_cnt[node];

    float ax = 0.0f, ay = 0.0f;
    for (int base = 0; base < cnt; base += 32) {
        int m = cnt - base; if (m > 32) m = 32;
        int r = 0; float nm = 0.0f;
        if (lane < m) {
            r  = g_erow[start + base + lane];
            nm = g_enorm[start + base + lane];
        }
        for (int j = 0; j < m; ++j) {
            int rr   = __shfl_sync(0xffffffffu, r, j);
            float w  = __shfl_sync(0xffffffffu, nm, j);
            float2 v = ((const float2*)(g_xw + (size_t)rr * CH))[lane];
            ax = fmaf(v.x, w, ax);
            ay = fmaf(v.y, w, ay);
        }
    }

    // + bias
    float2 bb = ((const float2*)b)[lane];
    float h0 = ax + bb.x, h1 = ay + bb.y;

    // LayerNorm over 64 channels
    float s = h0 + h1;
    #pragma unroll
    for (int o = 16; o > 0; o >>= 1) s += __shfl_xor_sync(0xffffffffu, s, o);
    float mu = s * (1.0f / 64.0f);
    float d0 = h0 - mu, d1 = h1 - mu;
    float vs = d0 * d0 + d1 * d1;
    #pragma unroll
    for (int o = 16; o > 0; o >>= 1) vs += __shfl_xor_sync(0xffffffffu, vs, o);
    float inv = rsqrtf(vs * (1.0f / 64.0f) + 1e-5f);

    float2 gg = ((const float2*)gamma)[lane];
    float2 be = ((const float2*)beta)[lane];
    float y0 = fmaf(d0 * inv, gg.x, be.x);
    float y1 = fmaf(d1 * inv, gg.y, be.y);
    y0 = __fdividef(y0, 1.0f + __expf(-y0));   // silu
    y1 = __fdividef(y1, 1.0f + __expf(-y1));

    float2 xv = ((const float2*)(x + (size_t)node * CH))[lane];
    float2 o2 = make_float2(y0 + xv.x, y1 + xv.y);
    ((float2*)(out + (size_t)node * CH))[lane] = o2;
}

// ---------------------------------------------------------------------------
extern "C" void kernel_launch(void* const* d_in, const int* in_sizes, int n_in,
                              void* d_out, int out_size) {
    const float* x     = (const float*)d_in[0];
    const void*  ei    = d_in[1];
    const float* ea    = (const float*)d_in[2];
    const float* W     = (const float*)d_in[3];
    const float* b     = (const float*)d_in[4];
    const float* W1    = (const float*)d_in[5];
    const float* b1    = (const float*)d_in[6];
    const float* W2    = (const float*)d_in[7];
    const float* b2    = (const float*)d_in[8];
    const float* gamma = (const float*)d_in[9];
    const float* beta  = (const float*)d_in[10];
    float* out = (float*)d_out;

    k_detect<<<1, 32>>>((const long long*)ei);
    k_init<<<(N_NODES + 255) / 256, 256>>>();
    k_xw<<<(N_NODES + 63) / 64, 256>>>(x, W);
    k_edge<<<(N_EDGES + 255) / 256, 256>>>(ea, ei, W1, b1, W2, b2);
    k_scan1<<<NB_SCAN, 1024>>>();
    k_scan2<<<1, 32>>>();
    k_final<<<(N_NODES + 255) / 256, 256>>>();
    k_place<<<(N_EDGES + 255) / 256, 256>>>(ei);
    k_gather_ln<<<(N_NODES + 7) / 8, 256>>>(x, b, gamma, beta, out);
}